// round 7
// baseline (speedup 1.0000x reference)
#include <cuda_runtime.h>
#include <cuda_fp16.h>
#include <cstdint>

// Problem constants (fixed by the dataset)
#define NN    50000
#define EE    800000
#define IN_F  96
#define HID_F 128
#define OUT_F 64
#define TT    8

#define SCAN_BLK 512
#define NBLK ((NN + SCAN_BLK - 1) / SCAN_BLK)    // 98

// ---------------- static device scratch (no allocations allowed) -------------
__device__ int      g_counts[NN];      // zero-init at load; re-zeroed by k_scan23
__device__ int      g_rowptr[NN + 1];
__device__ int      g_cursor[NN];
__device__ int      g_bsum[NBLK];
__device__ int2     g_epack[EE];                            // (src, w-as-bits)
__device__ __half   g_xh[(size_t)NN * IN_F];                // 9.6 MB fp16 x
__device__ __half   g_agg1h[(size_t)NN * IN_F];             // 9.6 MB fp16 agg1
__device__ __half   g_ph[(size_t)NN * TT * OUT_F];          // 51.2 MB, [n][t*64+c]
__device__ uint32_t g_B1h[TT * HID_F * 48];                 // fp16x2 [t][n][k2]
__device__ uint32_t g_B2h[TT * OUT_F * 64];                 // fp16x2 [t][n][k2]

// ---------------- helpers ------------------------------------------------------
__device__ __forceinline__ void mma_f16(float d[4],
                                        uint32_t a0, uint32_t a1, uint32_t a2, uint32_t a3,
                                        uint32_t b0, uint32_t b1) {
    asm volatile("mma.sync.aligned.m16n8k16.row.col.f32.f16.f16.f32 "
        "{%0,%1,%2,%3}, {%4,%5,%6,%7}, {%8,%9}, {%0,%1,%2,%3};"
        : "+f"(d[0]), "+f"(d[1]), "+f"(d[2]), "+f"(d[3])
        : "r"(a0), "r"(a1), "r"(a2), "r"(a3), "r"(b0), "r"(b1));
}
__device__ __forceinline__ uint32_t pack_h2(float a, float b) {
    __half2 h = __float22half2_rn(make_float2(a, b));
    return *(uint32_t*)&h;
}
// packed f32x2 FMA: acc += v * w2   (FFMA2, exact same numerics as 2x fmaf)
__device__ __forceinline__ void ffma2(unsigned long long& acc, float2 v,
                                      unsigned long long w2) {
    unsigned long long fv;
    asm("mov.b64 %0, {%1, %2};" : "=l"(fv) : "f"(v.x), "f"(v.y));
    asm("fma.rn.f32x2 %0, %1, %2, %0;" : "+l"(acc) : "l"(fv), "l"(w2));
}
__device__ __forceinline__ unsigned long long packww(float w) {
    unsigned long long u;
    asm("mov.b64 %0, {%1, %1};" : "=l"(u) : "f"(w));
    return u;
}
__device__ __forceinline__ float2 unpack2(unsigned long long u) {
    float2 f;
    asm("mov.b64 {%0, %1}, %2;" : "=f"(f.x), "=f"(f.y) : "l"(u));
    return f;
}

// ---------------- CSR build --------------------------------------------------
__global__ void k_hist(const int* __restrict__ dst) {
    int e = blockIdx.x * blockDim.x + threadIdx.x;
    if (e < EE) atomicAdd(&g_counts[dst[e]], 1);
}
__global__ void k_scan1() {
    __shared__ int s[SCAN_BLK];
    int b = blockIdx.x, tid = threadIdx.x;
    int i = b * SCAN_BLK + tid;
    s[tid] = (i < NN) ? g_counts[i] : 0;
    __syncthreads();
    #pragma unroll
    for (int off = SCAN_BLK / 2; off > 0; off >>= 1) {
        if (tid < off) s[tid] += s[tid + off];
        __syncthreads();
    }
    if (tid == 0) g_bsum[b] = s[0];
}
// combined: per-block redundant scan of the 98 block sums + local scan
__global__ void k_scan23() {
    __shared__ int s[SCAN_BLK];
    __shared__ int bs[128];
    __shared__ int boff;
    int b = blockIdx.x, tid = threadIdx.x;
    int i = b * SCAN_BLK + tid;
    int c = (i < NN) ? g_counts[i] : 0;
    s[tid] = c;
    if (tid < 128) bs[tid] = (tid < NBLK) ? g_bsum[tid] : 0;
    __syncthreads();
    // Hillis-Steele inclusive scan of bs by first 4 warps
    if (tid < 128) {
        #pragma unroll
        for (int off = 1; off < 128; off <<= 1) {
            int u = (tid >= off) ? bs[tid - off] : 0;
            __syncthreads();
            bs[tid] += u;
            __syncthreads();
        }
        if (tid == 0) boff = (b == 0) ? 0 : bs[b - 1];
    } else {
        #pragma unroll
        for (int off = 1; off < 128; off <<= 1) { __syncthreads(); __syncthreads(); }
    }
    __syncthreads();
    // local inclusive scan of s
    #pragma unroll
    for (int off = 1; off < SCAN_BLK; off <<= 1) {
        int u = (tid >= off) ? s[tid - off] : 0;
        __syncthreads();
        s[tid] += u;
        __syncthreads();
    }
    if (i < NN) {
        int excl = s[tid] - c + boff;
        g_rowptr[i] = excl;
        g_cursor[i] = excl;
        g_counts[i] = 0;                      // restore invariant for next call
        if (i == NN - 1) g_rowptr[NN] = excl + c;
    }
}
__global__ void k_scatter(const int* __restrict__ src, const int* __restrict__ dst,
                          const float* __restrict__ ew) {
    int e = blockIdx.x * blockDim.x + threadIdx.x;
    if (e >= EE) return;
    int d = dst[e];
    int pos = atomicAdd(&g_cursor[d], 1);
    g_epack[pos] = make_int2(src[e], __float_as_int(ew[e]));
}

// ---------------- convert: x->fp16 AND masked weights -> fp16x2 ----------------
#define XW (NN * IN_F / 2)                 // 2,400,000 half2
__global__ void k_convert(const float* __restrict__ x,
                          const float* __restrict__ W1, const float* __restrict__ W2,
                          const float* __restrict__ M1, const float* __restrict__ M2) {
    int i = blockIdx.x * blockDim.x + threadIdx.x;
    if (i < XW) {
        float2 v = *(const float2*)(x + i * 2);
        *((__half2*)g_xh + i) = __float22half2_rn(v);
    }
    const int S1 = TT * HID_F * 48;        // 49152
    const int S2 = TT * OUT_F * 64;        // 32768
    if (i < S1) {
        int t = i / (HID_F * 48);
        int rem = i % (HID_F * 48);
        int n = rem / 48, k2 = rem % 48;
        int e0 = (2 * k2) * HID_F + n;
        int e1 = e0 + HID_F;
        const float* m = M1 + (size_t)t * IN_F * HID_F;
        g_B1h[i] = pack_h2(W1[e0] * m[e0], W1[e1] * m[e1]);
    }
    if (i < S2) {
        int t = i / (OUT_F * 64);
        int rem = i % (OUT_F * 64);
        int n = rem / 64, k2 = rem % 64;
        int e0 = (2 * k2) * OUT_F + n;
        int e1 = e0 + OUT_F;
        const float* m = M2 + (size_t)t * HID_F * OUT_F;
        g_B2h[i] = pack_h2(W2[e0] * m[e0], W2[e1] * m[e1]);
    }
}

// ---------------- SpMM1: agg1h = spmm(xh), warp per node, unroll 4 ------------
__global__ void k_spmm96() {
    int warp = (blockIdx.x * blockDim.x + threadIdx.x) >> 5;
    int lane = threadIdx.x & 31;
    if (warp >= NN) return;
    int r0 = g_rowptr[warp], r1 = g_rowptr[warp + 1];
    const uint32_t* xh = (const uint32_t*)g_xh;     // half2 granules, 48/row
    const bool hi = lane < 16;

    unsigned long long A0 = 0, A1 = 0;              // f32x2 accumulators
    int r = r0;
    for (; r + 3 < r1; r += 4) {
        int2 e0 = g_epack[r],     e1 = g_epack[r + 1];
        int2 e2 = g_epack[r + 2], e3 = g_epack[r + 3];
        uint32_t u00 = xh[e0.x * 48 + lane];
        uint32_t u10 = xh[e1.x * 48 + lane];
        uint32_t u20 = xh[e2.x * 48 + lane];
        uint32_t u30 = xh[e3.x * 48 + lane];
        uint32_t u01 = hi ? xh[e0.x * 48 + 32 + lane] : 0u;
        uint32_t u11 = hi ? xh[e1.x * 48 + 32 + lane] : 0u;
        uint32_t u21 = hi ? xh[e2.x * 48 + 32 + lane] : 0u;
        uint32_t u31 = hi ? xh[e3.x * 48 + 32 + lane] : 0u;
        unsigned long long w0 = packww(__int_as_float(e0.y));
        unsigned long long w1 = packww(__int_as_float(e1.y));
        unsigned long long w2 = packww(__int_as_float(e2.y));
        unsigned long long w3 = packww(__int_as_float(e3.y));
        ffma2(A0, __half22float2(*(__half2*)&u00), w0);
        ffma2(A0, __half22float2(*(__half2*)&u10), w1);
        ffma2(A0, __half22float2(*(__half2*)&u20), w2);
        ffma2(A0, __half22float2(*(__half2*)&u30), w3);
        ffma2(A1, __half22float2(*(__half2*)&u01), w0);
        ffma2(A1, __half22float2(*(__half2*)&u11), w1);
        ffma2(A1, __half22float2(*(__half2*)&u21), w2);
        ffma2(A1, __half22float2(*(__half2*)&u31), w3);
    }
    for (; r < r1; r++) {
        int2 e = g_epack[r];
        unsigned long long w = packww(__int_as_float(e.y));
        uint32_t u0 = xh[e.x * 48 + lane];
        uint32_t u1 = hi ? xh[e.x * 48 + 32 + lane] : 0u;
        ffma2(A0, __half22float2(*(__half2*)&u0), w);
        ffma2(A1, __half22float2(*(__half2*)&u1), w);
    }
    float2 a0 = unpack2(A0), a1 = unpack2(A1);
    uint32_t* o = (uint32_t*)g_agg1h + (size_t)warp * 48;
    o[lane] = pack_h2(a0.x, a0.y);
    if (hi) o[32 + lane] = pack_h2(a1.x, a1.y);
}

// ---------------- SpMM2: out[t,n,:] = spmm(p_t) for ALL t, unroll 4 -----------
__device__ __forceinline__ void acc8(unsigned long long acc[8], int base, uint4 u,
                                     unsigned long long w2) {
    const __half2* h = (const __half2*)&u;
    #pragma unroll
    for (int q = 0; q < 4; q++)
        ffma2(acc[base + q], __half22float2(h[q]), w2);
}

__global__ void k_spmm_all(float* __restrict__ out) {
    int warp = (blockIdx.x * blockDim.x + threadIdx.x) >> 5;
    int lane = threadIdx.x & 31;
    if (warp >= NN) return;
    int r0 = g_rowptr[warp], r1 = g_rowptr[warp + 1];

    unsigned long long acc[8];
    #pragma unroll
    for (int i = 0; i < 8; i++) acc[i] = 0ull;

    int r = r0;
    for (; r + 3 < r1; r += 4) {
        int2 e0 = g_epack[r],     e1 = g_epack[r + 1];
        int2 e2 = g_epack[r + 2], e3 = g_epack[r + 3];
        const uint4* p0 = (const uint4*)(g_ph + (size_t)e0.x * 512) + lane * 2;
        const uint4* p1 = (const uint4*)(g_ph + (size_t)e1.x * 512) + lane * 2;
        const uint4* p2 = (const uint4*)(g_ph + (size_t)e2.x * 512) + lane * 2;
        const uint4* p3 = (const uint4*)(g_ph + (size_t)e3.x * 512) + lane * 2;
        uint4 u00 = p0[0], u01 = p0[1];
        uint4 u10 = p1[0], u11 = p1[1];
        uint4 u20 = p2[0], u21 = p2[1];
        uint4 u30 = p3[0], u31 = p3[1];
        unsigned long long w0 = packww(__int_as_float(e0.y));
        unsigned long long w1 = packww(__int_as_float(e1.y));
        unsigned long long w2 = packww(__int_as_float(e2.y));
        unsigned long long w3 = packww(__int_as_float(e3.y));
        acc8(acc, 0, u00, w0); acc8(acc, 4, u01, w0);
        acc8(acc, 0, u10, w1); acc8(acc, 4, u11, w1);
        acc8(acc, 0, u20, w2); acc8(acc, 4, u21, w2);
        acc8(acc, 0, u30, w3); acc8(acc, 4, u31, w3);
    }
    for (; r < r1; r++) {
        int2 e = g_epack[r];
        unsigned long long w = packww(__int_as_float(e.y));
        const uint4* p = (const uint4*)(g_ph + (size_t)e.x * 512) + lane * 2;
        uint4 u0 = p[0], u1 = p[1];
        acc8(acc, 0, u0, w); acc8(acc, 4, u1, w);
    }

    int t  = lane >> 2;
    int c0 = (lane & 3) * 16;
    float* op = out + ((size_t)t * NN + warp) * OUT_F + c0;
    #pragma unroll
    for (int q = 0; q < 4; q++) {
        float2 f0 = unpack2(acc[q * 2]);
        float2 f1 = unpack2(acc[q * 2 + 1]);
        *(float4*)(op + q * 4) = make_float4(f0.x, f0.y, f1.x, f1.y);
    }
}

// ---------------- fused fp16 mma GEMM (loop over all t per CTA) ---------------
#define OFF_A   0
#define LDA     52
#define OFF_B1  6656
#define LDB1    52
#define OFF_B2  13312
#define LDB2    68
#define OFF_H   17664
#define LDH     68
#define FUSED_WORDS (OFF_H + 128 * LDH)            // 26368 words
#define FUSED_SMEM  (FUSED_WORDS * 4)              // 105472 bytes

__global__ void __launch_bounds__(256, 2)
k_fused_gemm() {
    extern __shared__ uint32_t sm[];
    const int tid  = threadIdx.x;
    const int wid  = tid >> 5;
    const int lane = tid & 31;
    const int gid  = lane >> 2;
    const int tig  = lane & 3;
    const int row0 = blockIdx.x * 128;

    const uint32_t* ah = (const uint32_t*)g_agg1h;
    for (int e = tid; e < 128 * 48; e += 256) {
        int r = e / 48, k2 = e % 48;
        int gr = row0 + r;
        sm[OFF_A + r * LDA + k2] = (gr < NN) ? ah[gr * 48 + k2] : 0u;
    }

    const int r0 = wid * 16;
    const int rowA = row0 + r0 + gid;
    const int rowB = rowA + 8;

    for (int t = 0; t < TT; t++) {
        __syncthreads();
        {
            const uint32_t* b1 = g_B1h + t * HID_F * 48;
            for (int e = tid; e < HID_F * 48; e += 256)
                sm[OFF_B1 + (e / 48) * LDB1 + (e % 48)] = b1[e];
            const uint32_t* b2 = g_B2h + t * OUT_F * 64;
            for (int e = tid; e < OUT_F * 64; e += 256)
                sm[OFF_B2 + (e >> 6) * LDB2 + (e & 63)] = b2[e];
        }
        __syncthreads();

        // ===== GEMM1: H[128,128] = A[128,96] @ B1, 6 k16-steps =====
        float acc1[16][4];
        #pragma unroll
        for (int j = 0; j < 16; j++)
            #pragma unroll
            for (int i = 0; i < 4; i++) acc1[j][i] = 0.f;

        #pragma unroll
        for (int kb = 0; kb < 6; kb++) {
            const int k2b = kb * 8;
            uint32_t a0 = sm[OFF_A + (r0 + gid)     * LDA + k2b + tig];
            uint32_t a1 = sm[OFF_A + (r0 + gid + 8) * LDA + k2b + tig];
            uint32_t a2 = sm[OFF_A + (r0 + gid)     * LDA + k2b + tig + 4];
            uint32_t a3 = sm[OFF_A + (r0 + gid + 8) * LDA + k2b + tig + 4];
            #pragma unroll
            for (int j = 0; j < 16; j++) {
                uint32_t b0 = sm[OFF_B1 + (j * 8 + gid) * LDB1 + k2b + tig];
                uint32_t b1 = sm[OFF_B1 + (j * 8 + gid) * LDB1 + k2b + tig + 4];
                mma_f16(acc1[j], a0, a1, a2, a3, b0, b1);
            }
        }

        #pragma unroll
        for (int j = 0; j < 16; j++) {
            float f0 = acc1[j][0], f1 = acc1[j][1], f2 = acc1[j][2], f3 = acc1[j][3];
            uint32_t uA = pack_h2(f0 > 0.f ? f0 : 0.f, f1 > 0.f ? f1 : 0.f);
            uint32_t uB = pack_h2(f2 > 0.f ? f2 : 0.f, f3 > 0.f ? f3 : 0.f);
            sm[OFF_H + (r0 + gid)     * LDH + 4 * j + tig] = uA;
            sm[OFF_H + (r0 + gid + 8) * LDH + 4 * j + tig] = uB;
        }
        __syncwarp();

        // ===== GEMM2: P[128,64] = H[128,128] @ B2, 8 k16-steps =====
        float acc2[8][4];
        #pragma unroll
        for (int j = 0; j < 8; j++)
            #pragma unroll
            for (int i = 0; i < 4; i++) acc2[j][i] = 0.f;

        #pragma unroll
        for (int kb = 0; kb < 8; kb++) {
            const int k2b = kb * 8;
            uint32_t a0 = sm[OFF_H + (r0 + gid)     * LDH + k2b + tig];
            uint32_t a1 = sm[OFF_H + (r0 + gid + 8) * LDH + k2b + tig];
            uint32_t a2 = sm[OFF_H + (r0 + gid)     * LDH + k2b + tig + 4];
            uint32_t a3 = sm[OFF_H + (r0 + gid + 8) * LDH + k2b + tig + 4];
            #pragma unroll
            for (int j = 0; j < 8; j++) {
                uint32_t b0 = sm[OFF_B2 + (j * 8 + gid) * LDB2 + k2b + tig];
                uint32_t b1 = sm[OFF_B2 + (j * 8 + gid) * LDB2 + k2b + tig + 4];
                mma_f16(acc2[j], a0, a1, a2, a3, b0, b1);
            }
        }

        if (rowA < NN) {
            __half* p = g_ph + (size_t)rowA * 512 + t * 64;
            #pragma unroll
            for (int j = 0; j < 8; j++)
                *(uint32_t*)(p + j * 8 + 2 * tig) = pack_h2(acc2[j][0], acc2[j][1]);
        }
        if (rowB < NN) {
            __half* p = g_ph + (size_t)rowB * 512 + t * 64;
            #pragma unroll
            for (int j = 0; j < 8; j++)
                *(uint32_t*)(p + j * 8 + 2 * tig) = pack_h2(acc2[j][2], acc2[j][3]);
        }
    }
}

// ---------------- launch ------------------------------------------------------
extern "C" void kernel_launch(void* const* d_in, const int* in_sizes, int n_in,
                              void* d_out, int out_size) {
    (void)in_sizes; (void)n_in; (void)out_size;
    const float* x   = (const float*)d_in[0];
    const float* ew  = (const float*)d_in[1];
    const float* W1  = (const float*)d_in[2];
    const float* W2  = (const float*)d_in[3];
    const float* m1  = (const float*)d_in[4];
    const float* m2  = (const float*)d_in[5];
    const int*   src = (const int*)d_in[6];
    const int*   dst = (const int*)d_in[7];
    float* out = (float*)d_out;

    cudaFuncSetAttribute((const void*)k_fused_gemm,
                         cudaFuncAttributeMaxDynamicSharedMemorySize, FUSED_SMEM);

    // 1. CSR build + conversions
    k_hist<<<(EE + 255) / 256, 256>>>(dst);
    k_scan1<<<NBLK, SCAN_BLK>>>();
    k_scan23<<<NBLK, SCAN_BLK>>>();
    k_scatter<<<(EE + 255) / 256, 256>>>(src, dst, ew);
    k_convert<<<(XW + 255) / 256, 256>>>(x, W1, W2, m1, m2);

    // 2. agg1h = spmm(xh)
    k_spmm96<<<(NN * 32 + 255) / 256, 256>>>();

    // 3+4. fused fp16 mma: p_t = relu(agg1 @ B1_t) @ B2_t
    k_fused_gemm<<<(NN + 127) / 128, 256, FUSED_SMEM>>>();

    // 5. out = spmm(p) for all 8 samples in one pass
    k_spmm_all<<<(NN * 32 + 255) / 256, 256>>>(out);
}